// round 1
// baseline (speedup 1.0000x reference)
#include <cuda_runtime.h>
#include <cuda_bf16.h>

#define DT 0.01f

__global__ __launch_bounds__(128)
void eskf_kernel(const float* __restrict__ x,
                 const float* __restrict__ state,
                 const float* __restrict__ cov,
                 const float* __restrict__ Qm,
                 const float* __restrict__ Rm,
                 float* __restrict__ out, int B)
{
    int b = blockIdx.x * blockDim.x + threadIdx.x;
    if (b >= B) return;

    // ---- loads ----
    float meas[7], tw[6];
#pragma unroll
    for (int i = 0; i < 7; i++) meas[i] = x[(size_t)i * B + b];
#pragma unroll
    for (int i = 0; i < 6; i++) tw[i] = x[(size_t)(8 + i) * B + b];

    float st[7];
#pragma unroll
    for (int i = 0; i < 7; i++) st[i] = state[(size_t)b * 7 + i];

    // P = covariance + Q   (6x6) — both 144B-per-element, 16B aligned
    float P[6][6];
    {
        const float4* c4 = (const float4*)(cov + (size_t)b * 36);
        const float4* q4 = (const float4*)(Qm  + (size_t)b * 36);
        float* p = &P[0][0];
#pragma unroll
        for (int i = 0; i < 9; i++) {
            float4 a = c4[i], q = q4[i];
            p[i*4+0] = a.x + q.x;
            p[i*4+1] = a.y + q.y;
            p[i*4+2] = a.z + q.z;
            p[i*4+3] = a.w + q.w;
        }
    }
    const float* r = Rm + (size_t)b * 49;

    // ---- predict: inject(state, DT*twist) ----
    float pp0 = st[0] + DT * tw[0];
    float pp1 = st[1] + DT * tw[1];
    float pp2 = st[2] + DT * tw[2];
    float w1 = st[3], x1 = st[4], y1 = st[5], z1 = st[6];
    float dx = 0.5f * DT * tw[3], dy = 0.5f * DT * tw[4], dz = 0.5f * DT * tw[5];
    // quat_mul(q, (1,dx,dy,dz))
    float qw = w1      - x1*dx - y1*dy - z1*dz;
    float qx = w1*dx + x1      + y1*dz - z1*dy;
    float qy = w1*dy - x1*dz + y1      + z1*dx;
    float qz = w1*dz + x1*dy - y1*dx + z1;
    {
        float n = rsqrtf(qw*qw + qx*qx + qy*qy + qz*qz);
        qw *= n; qx *= n; qy *= n; qz *= n;
    }

    // ---- Qd(original q): 4x3 ----
    float Qd[4][3] = {
        {-0.5f*x1, -0.5f*y1, -0.5f*z1},
        { 0.5f*w1, -0.5f*z1,  0.5f*y1},
        { 0.5f*z1,  0.5f*w1, -0.5f*x1},
        {-0.5f*y1,  0.5f*x1,  0.5f*w1}};

    // ---- S = H P H^T + R, with H = [[I3,0],[0,Qd]] ----
    // Blocks: [[P_A,        P_B Qd^T ],
    //          [Qd P_C,     Qd P_D Qd^T]]
    float S[7][7];
#pragma unroll
    for (int i = 0; i < 3; i++)
#pragma unroll
        for (int j = 0; j < 3; j++)
            S[i][j] = P[i][j] + r[i*7 + j];
#pragma unroll
    for (int i = 0; i < 3; i++)
#pragma unroll
        for (int j = 0; j < 4; j++) {
            float s = P[i][3]*Qd[j][0] + P[i][4]*Qd[j][1] + P[i][5]*Qd[j][2];
            S[i][3 + j] = s + r[i*7 + 3 + j];
        }
    float M[4][6];                        // M = Qd @ P[3:6][:]
#pragma unroll
    for (int i = 0; i < 4; i++)
#pragma unroll
        for (int j = 0; j < 6; j++)
            M[i][j] = Qd[i][0]*P[3][j] + Qd[i][1]*P[4][j] + Qd[i][2]*P[5][j];
#pragma unroll
    for (int i = 0; i < 4; i++)
#pragma unroll
        for (int j = 0; j < 3; j++)
            S[3 + i][j] = M[i][j] + r[(3 + i)*7 + j];
#pragma unroll
    for (int i = 0; i < 4; i++)
#pragma unroll
        for (int j = 0; j < 4; j++) {
            float s = M[i][3]*Qd[j][0] + M[i][4]*Qd[j][1] + M[i][5]*Qd[j][2];
            S[3 + i][3 + j] = s + r[(3 + i)*7 + 3 + j];
        }

    // ---- innovation = measurement - predict_state ----
    float inn[7];
    inn[0] = meas[0] - pp0;
    inn[1] = meas[1] - pp1;
    inn[2] = meas[2] - pp2;
    inn[3] = meas[3] - qw;
    inn[4] = meas[4] - qx;
    inn[5] = meas[5] - qy;
    inn[6] = meas[6] - qz;

    // ---- solve S z = inn  (unpivoted LU; S is SPD) ----
#pragma unroll
    for (int k = 0; k < 7; k++) {
        float ipiv = __frcp_rn(S[k][k]);
        S[k][k] = ipiv;                    // stash reciprocal on diagonal
#pragma unroll
        for (int i = k + 1; i < 7; i++) {
            float f = S[i][k] * ipiv;
#pragma unroll
            for (int j = k + 1; j < 7; j++)
                S[i][j] -= f * S[k][j];
            inn[i] -= f * inn[k];
        }
    }
    float z[7];
#pragma unroll
    for (int k = 6; k >= 0; k--) {
        float s = inn[k];
#pragma unroll
        for (int j = k + 1; j < 7; j++)
            s -= S[k][j] * z[j];
        z[k] = s * S[k][k];
    }

    // ---- error_state = P @ (H^T z) ----
    float hty[6];
    hty[0] = z[0]; hty[1] = z[1]; hty[2] = z[2];
#pragma unroll
    for (int i = 0; i < 3; i++)
        hty[3 + i] = Qd[0][i]*z[3] + Qd[1][i]*z[4] + Qd[2][i]*z[5] + Qd[3][i]*z[6];

    float err[6];
#pragma unroll
    for (int i = 0; i < 6; i++) {
        float s = 0.f;
#pragma unroll
        for (int j = 0; j < 6; j++)
            s += P[i][j] * hty[j];
        err[i] = s;
    }

    // ---- new_state = inject(predict_state, error_state) ----
    float po0 = pp0 + err[0];
    float po1 = pp1 + err[1];
    float po2 = pp2 + err[2];
    float ex = 0.5f*err[3], ey = 0.5f*err[4], ez = 0.5f*err[5];
    float ow = qw      - qx*ex - qy*ey - qz*ez;
    float ox = qw*ex + qx      + qy*ez - qz*ey;
    float oy = qw*ey - qx*ez + qy      + qz*ex;
    float oz = qw*ez + qx*ey - qy*ex + qz;
    {
        float n = rsqrtf(ow*ow + ox*ox + oy*oy + oz*oz);
        ow *= n; ox *= n; oy *= n; oz *= n;
    }

    float* o = out + (size_t)b * 7;
    o[0] = po0; o[1] = po1; o[2] = po2;
    o[3] = ow;  o[4] = ox;  o[5] = oy;  o[6] = oz;
}

extern "C" void kernel_launch(void* const* d_in, const int* in_sizes, int n_in,
                              void* d_out, int out_size)
{
    const float* x     = (const float*)d_in[0];
    const float* state = (const float*)d_in[1];
    const float* cov   = (const float*)d_in[2];
    const float* Qm    = (const float*)d_in[3];
    const float* Rm    = (const float*)d_in[4];
    float* out = (float*)d_out;

    int B = in_sizes[0] / 14;
    int threads = 128;
    int blocks = (B + threads - 1) / threads;
    eskf_kernel<<<blocks, threads>>>(x, state, cov, Qm, Rm, out, B);
}

// round 2
// speedup vs baseline: 1.0053x; 1.0053x over previous
#include <cuda_runtime.h>
#include <cuda_bf16.h>

#define DT 0.01f
#define TPB 128

__global__ __launch_bounds__(TPB)
void eskf_kernel(const float* __restrict__ x,
                 const float* __restrict__ state,
                 const float* __restrict__ cov,
                 const float* __restrict__ Qm,
                 const float* __restrict__ Rm,
                 float* __restrict__ out, int B)
{
    __shared__ float sP[TPB * 36];   // P = cov + Q, flat per-element rows (144B stride)
    __shared__ float sR[TPB * 49];   // R flat (196B stride)
    __shared__ float sV[TPB * 7];    // state in / result out staging

    const int tid  = threadIdx.x;
    const int base = blockIdx.x * TPB;
    const int n    = min(TPB, B - base);

    // ================= coalesced staging =================
    if (n == TPB) {
        const float4* c4 = (const float4*)(cov + (size_t)base * 36);
        const float4* q4 = (const float4*)(Qm  + (size_t)base * 36);
        float4* p4 = (float4*)sP;
#pragma unroll
        for (int it = 0; it < 9; it++) {          // 128*36/4 = 1152 float4
            int i = it * TPB + tid;
            float4 a = c4[i], q = q4[i];
            p4[i] = make_float4(a.x + q.x, a.y + q.y, a.z + q.z, a.w + q.w);
        }
        const float4* r4 = (const float4*)(Rm + (size_t)base * 49);
        float4* sr4 = (float4*)sR;
#pragma unroll
        for (int it = 0; it < 13; it++) {         // 128*49/4 = 1568 float4
            int i = it * TPB + tid;
            if (i < TPB * 49 / 4) sr4[i] = r4[i];
        }
        const float4* s4 = (const float4*)(state + (size_t)base * 7);
        float4* sv4 = (float4*)sV;
#pragma unroll
        for (int it = 0; it < 2; it++) {          // 128*7/4 = 224 float4
            int i = it * TPB + tid;
            if (i < TPB * 7 / 4) sv4[i] = s4[i];
        }
    } else {
        for (int i = tid; i < n * 36; i += TPB)
            sP[i] = cov[(size_t)base * 36 + i] + Qm[(size_t)base * 36 + i];
        for (int i = tid; i < n * 49; i += TPB)
            sR[i] = Rm[(size_t)base * 49 + i];
        for (int i = tid; i < n * 7; i += TPB)
            sV[i] = state[(size_t)base * 7 + i];
    }
    __syncthreads();

    // ================= per-element compute =================
    if (tid < n) {
        const int b = base + tid;

        float meas[7], tw[6];
#pragma unroll
        for (int i = 0; i < 7; i++) meas[i] = x[(size_t)i * B + b];
#pragma unroll
        for (int i = 0; i < 6; i++) tw[i] = x[(size_t)(8 + i) * B + b];

        float st[7];
#pragma unroll
        for (int i = 0; i < 7; i++) st[i] = sV[tid * 7 + i];

        // P into registers: 9 conflict-free LDS.128 (144B row stride)
        float P[6][6];
        {
            const float4* prow = (const float4*)(sP + tid * 36);
            float* p = &P[0][0];
#pragma unroll
            for (int i = 0; i < 9; i++) {
                float4 v = prow[i];
                p[i*4+0] = v.x; p[i*4+1] = v.y; p[i*4+2] = v.z; p[i*4+3] = v.w;
            }
        }
        const float* r = sR + tid * 49;

        // ---- predict: inject(state, DT*twist) ----
        float pp0 = st[0] + DT * tw[0];
        float pp1 = st[1] + DT * tw[1];
        float pp2 = st[2] + DT * tw[2];
        float w1 = st[3], x1 = st[4], y1 = st[5], z1 = st[6];
        float dx = 0.5f * DT * tw[3], dy = 0.5f * DT * tw[4], dz = 0.5f * DT * tw[5];
        float qw = w1      - x1*dx - y1*dy - z1*dz;
        float qx = w1*dx + x1      + y1*dz - z1*dy;
        float qy = w1*dy - x1*dz + y1      + z1*dx;
        float qz = w1*dz + x1*dy - y1*dx + z1;
        {
            float nn = rsqrtf(qw*qw + qx*qx + qy*qy + qz*qz);
            qw *= nn; qx *= nn; qy *= nn; qz *= nn;
        }

        // ---- Qd(original q): 4x3 ----
        float Qd[4][3] = {
            {-0.5f*x1, -0.5f*y1, -0.5f*z1},
            { 0.5f*w1, -0.5f*z1,  0.5f*y1},
            { 0.5f*z1,  0.5f*w1, -0.5f*x1},
            {-0.5f*y1,  0.5f*x1,  0.5f*w1}};

        // ---- S = H P H^T + R, H = [[I3,0],[0,Qd]] ----
        float S[7][7];
#pragma unroll
        for (int i = 0; i < 3; i++)
#pragma unroll
            for (int j = 0; j < 3; j++)
                S[i][j] = P[i][j] + r[i*7 + j];
#pragma unroll
        for (int i = 0; i < 3; i++)
#pragma unroll
            for (int j = 0; j < 4; j++) {
                float s = P[i][3]*Qd[j][0] + P[i][4]*Qd[j][1] + P[i][5]*Qd[j][2];
                S[i][3 + j] = s + r[i*7 + 3 + j];
            }
        float M[4][6];                    // M = Qd @ P[3:6][:]
#pragma unroll
        for (int i = 0; i < 4; i++)
#pragma unroll
            for (int j = 0; j < 6; j++)
                M[i][j] = Qd[i][0]*P[3][j] + Qd[i][1]*P[4][j] + Qd[i][2]*P[5][j];
#pragma unroll
        for (int i = 0; i < 4; i++)
#pragma unroll
            for (int j = 0; j < 3; j++)
                S[3 + i][j] = M[i][j] + r[(3 + i)*7 + j];
#pragma unroll
        for (int i = 0; i < 4; i++)
#pragma unroll
            for (int j = 0; j < 4; j++) {
                float s = M[i][3]*Qd[j][0] + M[i][4]*Qd[j][1] + M[i][5]*Qd[j][2];
                S[3 + i][3 + j] = s + r[(3 + i)*7 + 3 + j];
            }

        // ---- innovation ----
        float inn[7];
        inn[0] = meas[0] - pp0;
        inn[1] = meas[1] - pp1;
        inn[2] = meas[2] - pp2;
        inn[3] = meas[3] - qw;
        inn[4] = meas[4] - qx;
        inn[5] = meas[5] - qy;
        inn[6] = meas[6] - qz;

        // ---- solve S z = inn (unpivoted LU; S SPD) ----
#pragma unroll
        for (int k = 0; k < 7; k++) {
            float ipiv = __frcp_rn(S[k][k]);
            S[k][k] = ipiv;
#pragma unroll
            for (int i = k + 1; i < 7; i++) {
                float f = S[i][k] * ipiv;
#pragma unroll
                for (int j = k + 1; j < 7; j++)
                    S[i][j] -= f * S[k][j];
                inn[i] -= f * inn[k];
            }
        }
        float z[7];
#pragma unroll
        for (int k = 6; k >= 0; k--) {
            float s = inn[k];
#pragma unroll
            for (int j = k + 1; j < 7; j++)
                s -= S[k][j] * z[j];
            z[k] = s * S[k][k];
        }

        // ---- error_state = P @ (H^T z) ----
        float hty[6];
        hty[0] = z[0]; hty[1] = z[1]; hty[2] = z[2];
#pragma unroll
        for (int i = 0; i < 3; i++)
            hty[3 + i] = Qd[0][i]*z[3] + Qd[1][i]*z[4] + Qd[2][i]*z[5] + Qd[3][i]*z[6];

        float err[6];
#pragma unroll
        for (int i = 0; i < 6; i++) {
            float s = 0.f;
#pragma unroll
            for (int j = 0; j < 6; j++)
                s += P[i][j] * hty[j];
            err[i] = s;
        }

        // ---- new_state = inject(predict, err) ----
        float po0 = pp0 + err[0];
        float po1 = pp1 + err[1];
        float po2 = pp2 + err[2];
        float ex = 0.5f*err[3], ey = 0.5f*err[4], ez = 0.5f*err[5];
        float ow = qw      - qx*ex - qy*ey - qz*ez;
        float ox = qw*ex + qx      + qy*ez - qz*ey;
        float oy = qw*ey - qx*ez + qy      + qz*ex;
        float oz = qw*ez + qx*ey - qy*ex + qz;
        {
            float nn = rsqrtf(ow*ow + ox*ox + oy*oy + oz*oz);
            ow *= nn; ox *= nn; oy *= nn; oz *= nn;
        }

        // stage result (thread-private row of sV; no race with own read)
        float* o = sV + tid * 7;
        o[0] = po0; o[1] = po1; o[2] = po2;
        o[3] = ow;  o[4] = ox;  o[5] = oy;  o[6] = oz;
    }
    __syncthreads();

    // ================= coalesced store =================
    if (n == TPB) {
        float4* o4 = (float4*)(out + (size_t)base * 7);
        const float4* sv4 = (const float4*)sV;
#pragma unroll
        for (int it = 0; it < 2; it++) {
            int i = it * TPB + tid;
            if (i < TPB * 7 / 4) o4[i] = sv4[i];
        }
    } else {
        for (int i = tid; i < n * 7; i += TPB)
            out[(size_t)base * 7 + i] = sV[i];
    }
}

extern "C" void kernel_launch(void* const* d_in, const int* in_sizes, int n_in,
                              void* d_out, int out_size)
{
    const float* x     = (const float*)d_in[0];
    const float* state = (const float*)d_in[1];
    const float* cov   = (const float*)d_in[2];
    const float* Qm    = (const float*)d_in[3];
    const float* Rm    = (const float*)d_in[4];
    float* out = (float*)d_out;

    int B = in_sizes[0] / 14;
    int blocks = (B + TPB - 1) / TPB;
    eskf_kernel<<<blocks, TPB>>>(x, state, cov, Qm, Rm, out, B);
}

// round 3
// speedup vs baseline: 1.7232x; 1.7140x over previous
#include <cuda_runtime.h>
#include <cuda_bf16.h>

#define DT 0.01f
#define TPB 128

// lower-triangular flat index, i >= j
#define SIx(i, j) s[((i) * ((i) + 1)) / 2 + (j)]

__global__ __launch_bounds__(TPB, 5)
void eskf_kernel(const float* __restrict__ x,
                 const float* __restrict__ state,
                 const float* __restrict__ cov,
                 const float* __restrict__ Qm,
                 const float* __restrict__ Rm,
                 float* __restrict__ out, int B)
{
    int b = blockIdx.x * TPB + threadIdx.x;
    if (b >= B) return;

    // ---- twist + state ----
    float tw[6];
#pragma unroll
    for (int i = 0; i < 6; i++) tw[i] = x[(size_t)(8 + i) * B + b];

    float st[7];
#pragma unroll
    for (int i = 0; i < 7; i++) st[i] = state[(size_t)b * 7 + i];

    // ---- P = cov + Q (6x6), vectorized per-thread contiguous loads ----
    float P[6][6];
    {
        const float4* c4 = (const float4*)(cov + (size_t)b * 36);
        const float4* q4 = (const float4*)(Qm  + (size_t)b * 36);
        float* p = &P[0][0];
#pragma unroll
        for (int i = 0; i < 9; i++) {
            float4 a = c4[i], q = q4[i];
            p[i*4+0] = a.x + q.x;
            p[i*4+1] = a.y + q.y;
            p[i*4+2] = a.z + q.z;
            p[i*4+3] = a.w + q.w;
        }
    }
    const float* r = Rm + (size_t)b * 49;

    // ---- predict: inject(state, DT*twist) ----
    float pp0 = st[0] + DT * tw[0];
    float pp1 = st[1] + DT * tw[1];
    float pp2 = st[2] + DT * tw[2];
    float w1 = st[3], x1 = st[4], y1 = st[5], z1 = st[6];
    float dx = 0.5f * DT * tw[3], dy = 0.5f * DT * tw[4], dz = 0.5f * DT * tw[5];
    float qw = w1      - x1*dx - y1*dy - z1*dz;
    float qx = w1*dx + x1      + y1*dz - z1*dy;
    float qy = w1*dy - x1*dz + y1      + z1*dx;
    float qz = w1*dz + x1*dy - y1*dx + z1;
    {
        float nn = rsqrtf(qw*qw + qx*qx + qy*qy + qz*qz);
        qw *= nn; qx *= nn; qy *= nn; qz *= nn;
    }

    // ---- Qd(original q): 4x3 ----
    float Qd[4][3] = {
        {-0.5f*x1, -0.5f*y1, -0.5f*z1},
        { 0.5f*w1, -0.5f*z1,  0.5f*y1},
        { 0.5f*z1,  0.5f*w1, -0.5f*x1},
        {-0.5f*y1,  0.5f*x1,  0.5f*w1}};

    // ---- S = H P H^T + R (symmetric -> lower triangle only) ----
    // H = [[I3,0],[0,Qd]]; blocks: [[P_A, .],[Qd P_C, Qd P_D Qd^T]]
    float s[28];
#pragma unroll
    for (int i = 0; i < 3; i++)
#pragma unroll
        for (int j = 0; j <= i; j++)
            SIx(i, j) = P[i][j] + r[i*7 + j];

    float M[4][6];                    // M = Qd @ P[3:6][:]
#pragma unroll
    for (int a = 0; a < 4; a++)
#pragma unroll
        for (int j = 0; j < 6; j++)
            M[a][j] = Qd[a][0]*P[3][j] + Qd[a][1]*P[4][j] + Qd[a][2]*P[5][j];

#pragma unroll
    for (int a = 0; a < 4; a++)
#pragma unroll
        for (int j = 0; j < 3; j++)
            SIx(3 + a, j) = M[a][j] + r[(3 + a)*7 + j];

#pragma unroll
    for (int a = 0; a < 4; a++)
#pragma unroll
        for (int bb = 0; bb <= a; bb++)
            SIx(3 + a, 3 + bb) = M[a][3]*Qd[bb][0] + M[a][4]*Qd[bb][1]
                               + M[a][5]*Qd[bb][2] + r[(3 + a)*7 + 3 + bb];

    // ---- LDL^T factorization in place (S SPD) ----
    // strict lower <- L, diagonal <- 1/d
#pragma unroll
    for (int k = 0; k < 7; k++) {
        float dinv = __frcp_rn(SIx(k, k));
        float lcol[7];
#pragma unroll
        for (int i = k + 1; i < 7; i++)
            lcol[i] = SIx(i, k) * dinv;
#pragma unroll
        for (int i = k + 1; i < 7; i++)
#pragma unroll
            for (int j = k + 1; j <= i; j++)
                SIx(i, j) -= lcol[i] * SIx(j, k);
#pragma unroll
        for (int i = k + 1; i < 7; i++)
            SIx(i, k) = lcol[i];
        SIx(k, k) = dinv;
    }

    // ---- innovation (meas loaded late to cut peak reg pressure) ----
    float u[7];
    u[0] = x[(size_t)0 * B + b] - pp0;
    u[1] = x[(size_t)1 * B + b] - pp1;
    u[2] = x[(size_t)2 * B + b] - pp2;
    u[3] = x[(size_t)3 * B + b] - qw;
    u[4] = x[(size_t)4 * B + b] - qx;
    u[5] = x[(size_t)5 * B + b] - qy;
    u[6] = x[(size_t)6 * B + b] - qz;

    // ---- solve L D L^T z = u ----
#pragma unroll
    for (int k = 1; k < 7; k++)
#pragma unroll
        for (int j = 0; j < k; j++)
            u[k] -= SIx(k, j) * u[j];
#pragma unroll
    for (int k = 0; k < 7; k++)
        u[k] *= SIx(k, k);
    float z[7];
#pragma unroll
    for (int k = 6; k >= 0; k--) {
        float v = u[k];
#pragma unroll
        for (int j = k + 1; j < 7; j++)
            v -= SIx(j, k) * z[j];
        z[k] = v;
    }

    // ---- error_state = P @ (H^T z) ----
    float hty[6];
    hty[0] = z[0]; hty[1] = z[1]; hty[2] = z[2];
#pragma unroll
    for (int i = 0; i < 3; i++)
        hty[3 + i] = Qd[0][i]*z[3] + Qd[1][i]*z[4] + Qd[2][i]*z[5] + Qd[3][i]*z[6];

    float err[6];
#pragma unroll
    for (int i = 0; i < 6; i++) {
        float v = 0.f;
#pragma unroll
        for (int j = 0; j < 6; j++)
            v += P[i][j] * hty[j];
        err[i] = v;
    }

    // ---- new_state = inject(predict, err) ----
    float po0 = pp0 + err[0];
    float po1 = pp1 + err[1];
    float po2 = pp2 + err[2];
    float ex = 0.5f*err[3], ey = 0.5f*err[4], ez = 0.5f*err[5];
    float ow = qw      - qx*ex - qy*ey - qz*ez;
    float ox = qw*ex + qx      + qy*ez - qz*ey;
    float oy = qw*ey - qx*ez + qy      + qz*ex;
    float oz = qw*ez + qx*ey - qy*ex + qz;
    {
        float nn = rsqrtf(ow*ow + ox*ox + oy*oy + oz*oz);
        ow *= nn; ox *= nn; oy *= nn; oz *= nn;
    }

    float* o = out + (size_t)b * 7;
    o[0] = po0; o[1] = po1; o[2] = po2;
    o[3] = ow;  o[4] = ox;  o[5] = oy;  o[6] = oz;
}

extern "C" void kernel_launch(void* const* d_in, const int* in_sizes, int n_in,
                              void* d_out, int out_size)
{
    const float* x     = (const float*)d_in[0];
    const float* state = (const float*)d_in[1];
    const float* cov   = (const float*)d_in[2];
    const float* Qm    = (const float*)d_in[3];
    const float* Rm    = (const float*)d_in[4];
    float* out = (float*)d_out;

    int B = in_sizes[0] / 14;
    int blocks = (B + TPB - 1) / TPB;
    eskf_kernel<<<blocks, TPB>>>(x, state, cov, Qm, Rm, out, B);
}